// round 1
// baseline (speedup 1.0000x reference)
#include <cuda_runtime.h>

// WeightedDistanceTransform: exact 2D EDT per [256,256] slice, weighted,
// per-slice max, inverted normalize. One CTA per (b,c) slice.
//
// Phase 1: pack mask (flood != 0) into an 8KB shared bitmask.
// Phase 2 (pass A): exact horizontal nearest-zero distance g via outward
//                   expansion (first zero found == exact distance). g <= 512 (BIG).
// Phase 3 (pass B): exact vertical min-plus d2[r] = min_r' g[r']^2 + (r-r')^2
//                   with the sound early-exit d^2 >= best. Writes dt = w_c*sqrt(d2)
//                   to gmem and tracks the per-slice max.
// Phase 4: block max-reduction, then normalized rewrite (mx - dt)/mx (0 if mx==0).

#define HH 256
#define WW 256
#define NPIX (HH * WW)
#define NTHREADS 1024
#define ITERS (NPIX / NTHREADS)   // 64
#define BIG 512                   // matches reference BIG = H + W

#define SMEM_MASK_BYTES (NPIX / 8)            // 8192
#define SMEM_G_BYTES    (NPIX * 2)            // 131072 (uint16 g)
#define SMEM_RED_BYTES  (32 * 4)
#define SMEM_TOTAL (SMEM_MASK_BYTES + SMEM_G_BYTES + SMEM_RED_BYTES)

__global__ __launch_bounds__(NTHREADS, 1)
void wdt_kernel(const float* __restrict__ in, float* __restrict__ out) {
    extern __shared__ unsigned char smem_raw[];
    unsigned int*   maskbits = reinterpret_cast<unsigned int*>(smem_raw);                  // 2048 words
    unsigned short* g        = reinterpret_cast<unsigned short*>(smem_raw + SMEM_MASK_BYTES);
    float*          red      = reinterpret_cast<float*>(smem_raw + SMEM_MASK_BYTES + SMEM_G_BYTES);

    const int slice = blockIdx.x;
    const float* __restrict__ src = in  + (size_t)slice * NPIX;
    float*       __restrict__ dst = out + (size_t)slice * NPIX;

    const int tid  = threadIdx.x;
    const int lane = tid & 31;
    const int warp = tid >> 5;

    // ---- Phase 1: build shared bitmask (1 = foreground/nonzero) ----
    #pragma unroll
    for (int it = 0; it < ITERS; ++it) {
        int i = it * NTHREADS + tid;
        float v = src[i];
        unsigned b = __ballot_sync(0xffffffffu, v != 0.0f);
        if (lane == 0) maskbits[i >> 5] = b;
    }
    __syncthreads();

    // ---- Phase 2: pass A — exact horizontal nearest-zero distance ----
    for (int it = 0; it < ITERS; ++it) {
        int i = it * NTHREADS + tid;
        int w = i & (WW - 1);
        int rowbase = i - w;
        unsigned short gv;
        if (((maskbits[i >> 5] >> (i & 31)) & 1u) == 0u) {
            gv = 0;                               // background pixel: distance 0
        } else {
            gv = BIG;                             // no zero in this row -> BIG
            for (int d = 1; d < WW; ++d) {
                int l = w - d, r = w + d;
                bool any = false;
                if (l >= 0) {
                    int j = rowbase + l;
                    if (((maskbits[j >> 5] >> (j & 31)) & 1u) == 0u) { gv = (unsigned short)d; break; }
                    any = true;
                }
                if (r < WW) {
                    int j = rowbase + r;
                    if (((maskbits[j >> 5] >> (j & 31)) & 1u) == 0u) { gv = (unsigned short)d; break; }
                    any = true;
                }
                if (!any) break;                  // both sides out of range
            }
        }
        g[i] = gv;
    }
    __syncthreads();

    // per-channel weight (C = 3)
    const float wts[3] = {0.5f, 1.0f, 2.0f};
    const float wc = wts[slice % 3];

    // ---- Phase 3: pass B — exact vertical min-plus with sound early exit ----
    float lmax = 0.0f;
    for (int it = 0; it < ITERS; ++it) {
        int i = it * NTHREADS + tid;
        int w = i & (WW - 1);
        int r = i >> 8;
        int gv   = (int)g[i];
        int best = gv * gv;
        for (int d = 1; d < HH; ++d) {
            int dd = d * d;
            if (dd >= best) break;                // cannot improve: g^2 >= 0
            int up = r - d, dn = r + d;
            if (up >= 0) {
                int c = (int)g[up * WW + w];
                int cand = c * c + dd;
                best = min(best, cand);
            }
            if (dn < HH) {
                int c = (int)g[dn * WW + w];
                int cand = c * c + dd;
                best = min(best, cand);
            }
        }
        float dt = wc * sqrtf((float)best);
        dst[i] = dt;
        lmax = fmaxf(lmax, dt);
    }

    // ---- Phase 4: block max reduction ----
    #pragma unroll
    for (int o = 16; o; o >>= 1) lmax = fmaxf(lmax, __shfl_xor_sync(0xffffffffu, lmax, o));
    if (lane == 0) red[warp] = lmax;
    __syncthreads();
    if (warp == 0) {
        float v = red[lane];                      // 32 warps exactly
        #pragma unroll
        for (int o = 16; o; o >>= 1) v = fmaxf(v, __shfl_xor_sync(0xffffffffu, v, o));
        if (lane == 0) red[0] = v;
    }
    __syncthreads();

    const float mx  = red[0];
    const float inv = (mx > 0.0f) ? (1.0f / mx) : 0.0f;   // mx==0 -> all dt==0 -> out 0

    // ---- normalized rewrite: (mx - dt) / mx ----
    for (int it = 0; it < ITERS; ++it) {
        int i = it * NTHREADS + tid;
        float v = dst[i];
        dst[i] = (mx - v) * inv;
    }
}

extern "C" void kernel_launch(void* const* d_in, const int* in_sizes, int n_in,
                              void* d_out, int out_size) {
    const float* in = (const float*)d_in[0];
    float* out = (float*)d_out;
    int nslices = in_sizes[0] / NPIX;             // 48 for [16,3,256,256]

    cudaFuncSetAttribute(wdt_kernel, cudaFuncAttributeMaxDynamicSharedMemorySize, SMEM_TOTAL);
    wdt_kernel<<<nslices, NTHREADS, SMEM_TOTAL>>>(in, out);
}

// round 2
// speedup vs baseline: 2.7275x; 2.7275x over previous
#include <cuda_runtime.h>

// WeightedDistanceTransform — 3-kernel pipeline, ~768 CTAs per kernel.
// k1: exact horizontal nearest-zero distance via bitmask clz/ffs (pass A) -> g scratch
// k2: exact vertical min-plus with sound early exit (pass B) -> dt + per-slice atomicMax
// k3: inverted normalize (mx - dt)/mx.

#define HH 256
#define WW 256
#define NPIX (HH * WW)
#define BIG 512
#define MAXSLICES 64

__device__ unsigned short g_scratch[MAXSLICES * NPIX];   // 8 MB scratch (static, allowed)
__device__ unsigned int   mx_bits[MAXSLICES];

// ---------------- Kernel 1: pass A ----------------
#define K1_ROWS 16
#define K1_THREADS 256

__global__ __launch_bounds__(K1_THREADS)
void k1_passA(const float* __restrict__ in) {
    __shared__ unsigned int M[K1_ROWS * 8];       // foreground bitmask, 8 words/row
    const int blocksPerSlice = HH / K1_ROWS;      // 16
    const int slice = blockIdx.x / blocksPerSlice;
    const int rb    = blockIdx.x % blocksPerSlice;
    const int r0    = rb * K1_ROWS;
    const int tid   = threadIdx.x;
    const int lane  = tid & 31;

    if (rb == 0 && tid == 0) mx_bits[slice] = 0u;  // reset per replay (before k2 runs)

    const float* src = in + (size_t)slice * NPIX + (size_t)r0 * WW;
    unsigned short* gdst = g_scratch + (size_t)slice * NPIX + (size_t)r0 * WW;

    #pragma unroll
    for (int it = 0; it < (K1_ROWS * WW) / K1_THREADS; ++it) {
        int i = it * K1_THREADS + tid;
        float v = src[i];
        unsigned b = __ballot_sync(0xffffffffu, v != 0.0f);
        if (lane == 0) M[i >> 5] = b;
    }
    __syncthreads();

    #pragma unroll
    for (int it = 0; it < (K1_ROWS * WW) / K1_THREADS; ++it) {
        int i  = it * K1_THREADS + tid;
        int rl = i >> 8;                           // local row
        int w  = i & 255;
        const unsigned int* Mr = M + rl * 8;
        int ci = w >> 5, b = w & 31;

        // nearest zero at or left of w
        int ld = BIG;
        unsigned lmask = (b == 31) ? 0xffffffffu : ((2u << b) - 1u);
        unsigned z = (~Mr[ci]) & lmask;
        if (z) {
            ld = b - (31 - __clz(z));
        } else {
            for (int cj = ci - 1; cj >= 0; --cj) {
                unsigned zz = ~Mr[cj];
                if (zz) { ld = (ci - cj) * 32 + b - (31 - __clz(zz)); break; }
            }
        }
        // nearest zero at or right of w
        int rd = BIG;
        z = (~Mr[ci]) >> b;
        if (z) {
            rd = __ffs(z) - 1;
        } else {
            for (int cj = ci + 1; cj < 8; ++cj) {
                unsigned zz = ~Mr[cj];
                if (zz) { rd = cj * 32 + (__ffs(zz) - 1) - w; break; }
            }
        }
        int g = min(min(ld, rd), BIG);             // BIG if row has no zero (matches ref)
        gdst[i] = (unsigned short)g;
    }
}

// ---------------- Kernel 2: pass B ----------------
#define K2_COLS 16
#define K2_THREADS 256

__global__ __launch_bounds__(K2_THREADS)
void k2_passB(float* __restrict__ out) {
    __shared__ unsigned short gt[HH * K2_COLS];   // 8 KB tile: [row][col]
    __shared__ float red[K2_THREADS / 32];
    const int stripsPerSlice = WW / K2_COLS;      // 16
    const int slice = blockIdx.x / stripsPerSlice;
    const int st    = blockIdx.x % stripsPerSlice;
    const int c0    = st * K2_COLS;
    const int tid   = threadIdx.x;

    const unsigned short* gsrc = g_scratch + (size_t)slice * NPIX;

    // load 256x16 uint16 tile as uint32 words
    #pragma unroll
    for (int idx = 0; idx < (HH * K2_COLS / 2) / K2_THREADS; ++idx) {
        int j = idx * K2_THREADS + tid;
        int r = j >> 3, ww = j & 7;
        unsigned int v = *reinterpret_cast<const unsigned int*>(gsrc + r * WW + c0 + ww * 2);
        reinterpret_cast<unsigned int*>(gt)[r * (K2_COLS / 2) + ww] = v;
    }
    __syncthreads();

    const float wts[3] = {0.5f, 1.0f, 2.0f};
    const float wc = wts[slice % 3];
    float* dst = out + (size_t)slice * NPIX;

    float lmax = 0.0f;
    #pragma unroll
    for (int it = 0; it < (HH * K2_COLS) / K2_THREADS; ++it) {
        int i = it * K2_THREADS + tid;
        int r = i >> 4, c = i & 15;
        int gv   = (int)gt[r * K2_COLS + c];
        int best = gv * gv;
        for (int d = 1; d < HH; ++d) {
            int dd = d * d;
            if (dd >= best) break;                // exact: candidates are >= d^2
            int up = r - d, dn = r + d;
            if (up >= 0) { int cu = (int)gt[up * K2_COLS + c]; best = min(best, cu * cu + dd); }
            if (dn < HH) { int cd = (int)gt[dn * K2_COLS + c]; best = min(best, cd * cd + dd); }
        }
        float dt = wc * sqrtf((float)best);
        dst[r * WW + c0 + c] = dt;
        lmax = fmaxf(lmax, dt);
    }

    #pragma unroll
    for (int o = 16; o; o >>= 1) lmax = fmaxf(lmax, __shfl_xor_sync(0xffffffffu, lmax, o));
    if ((tid & 31) == 0) red[tid >> 5] = lmax;
    __syncthreads();
    if (tid < 8) {
        float v = red[tid];
        #pragma unroll
        for (int o = 4; o; o >>= 1) v = fmaxf(v, __shfl_xor_sync(0x000000ffu, v, o));
        if (tid == 0) atomicMax(&mx_bits[slice], __float_as_uint(v));  // dt>=0: bit-monotone
    }
}

// ---------------- Kernel 3: normalize ----------------
#define K3_THREADS 256

__global__ __launch_bounds__(K3_THREADS)
void k3_norm(float* __restrict__ out) {
    const int slice = blockIdx.x >> 4;            // 16 blocks per slice (16384 float4)
    const int bl    = blockIdx.x & 15;
    const float mx  = __uint_as_float(mx_bits[slice]);
    const float inv = (mx > 0.0f) ? (1.0f / mx) : 0.0f;   // mx==0 -> dt==0 -> out 0

    float4* p = reinterpret_cast<float4*>(out) + (size_t)slice * (NPIX / 4) + bl * 1024;
    #pragma unroll
    for (int k = 0; k < 4; ++k) {
        int j = k * K3_THREADS + threadIdx.x;
        float4 v = p[j];
        v.x = (mx - v.x) * inv;
        v.y = (mx - v.y) * inv;
        v.z = (mx - v.z) * inv;
        v.w = (mx - v.w) * inv;
        p[j] = v;
    }
}

extern "C" void kernel_launch(void* const* d_in, const int* in_sizes, int n_in,
                              void* d_out, int out_size) {
    const float* in = (const float*)d_in[0];
    float* out = (float*)d_out;
    const int nslices = in_sizes[0] / NPIX;       // 48 for [16,3,256,256]

    k1_passA<<<nslices * (HH / K1_ROWS), K1_THREADS>>>(in);
    k2_passB<<<nslices * (WW / K2_COLS), K2_THREADS>>>(out);
    k3_norm <<<nslices * 16,             K3_THREADS>>>(out);
}

// round 3
// speedup vs baseline: 2.7585x; 1.0114x over previous
#include <cuda_runtime.h>

// WeightedDistanceTransform — 3-kernel pipeline.
// k1: vectorized mask build (float4, arithmetic bit-pack, MLP>=4) + exact
//     horizontal nearest-zero distance via bitmask clz/ffs  -> g scratch (u16)
// k2: exact vertical min-plus with sound early exit -> dt + per-slice atomicMax
// k3: inverted normalize (mx - dt)/mx.

#define HH 256
#define WW 256
#define NPIX (HH * WW)
#define BIG 512
#define MAXSLICES 64

__device__ unsigned short g_scratch[MAXSLICES * NPIX];
__device__ unsigned int   mx_bits[MAXSLICES];

// ---------------- Kernel 1: pass A ----------------
#define K1_ROWS 16
#define K1_THREADS 256

__global__ __launch_bounds__(K1_THREADS)
void k1_passA(const float* __restrict__ in) {
    __shared__ unsigned int M[K1_ROWS * 8];       // foreground bitmask, 8 words/row
    const int blocksPerSlice = HH / K1_ROWS;      // 16
    const int slice = blockIdx.x / blocksPerSlice;
    const int rb    = blockIdx.x % blocksPerSlice;
    const int r0    = rb * K1_ROWS;
    const int tid   = threadIdx.x;

    if (rb == 0 && tid == 0) mx_bits[slice] = 0u;  // reset before k2 runs

    const float* src = in + (size_t)slice * NPIX + (size_t)r0 * WW;
    unsigned short* gdst = g_scratch + (size_t)slice * NPIX + (size_t)r0 * WW;

    // ---- mask build: 16 px/thread via 4 independent float4 loads ----
    {
        const float4* s4 = reinterpret_cast<const float4*>(src) + tid * 4;  // 16 floats
        float4 a = s4[0], b = s4[1], c = s4[2], d = s4[3];
        unsigned m = 0;
        m |= (a.x != 0.0f) << 0;  m |= (a.y != 0.0f) << 1;
        m |= (a.z != 0.0f) << 2;  m |= (a.w != 0.0f) << 3;
        m |= (b.x != 0.0f) << 4;  m |= (b.y != 0.0f) << 5;
        m |= (b.z != 0.0f) << 6;  m |= (b.w != 0.0f) << 7;
        m |= (c.x != 0.0f) << 8;  m |= (c.y != 0.0f) << 9;
        m |= (c.z != 0.0f) << 10; m |= (c.w != 0.0f) << 11;
        m |= (d.x != 0.0f) << 12; m |= (d.y != 0.0f) << 13;
        m |= (d.z != 0.0f) << 14; m |= (d.w != 0.0f) << 15;
        unsigned other = __shfl_xor_sync(0xffffffffu, m, 1);
        if ((tid & 1) == 0) M[tid >> 1] = m | (other << 16);   // even lane = low half
    }
    __syncthreads();

    // ---- pass A scan: 16 px/thread, clz/ffs on bitmask ----
    #pragma unroll
    for (int it = 0; it < (K1_ROWS * WW) / K1_THREADS; ++it) {
        int i  = it * K1_THREADS + tid;
        int rl = i >> 8;
        int w  = i & 255;
        const unsigned int* Mr = M + rl * 8;
        int ci = w >> 5, b = w & 31;

        int ld = BIG;                                          // nearest zero <= w
        unsigned lmask = (b == 31) ? 0xffffffffu : ((2u << b) - 1u);
        unsigned z = (~Mr[ci]) & lmask;
        if (z) {
            ld = b - (31 - __clz(z));
        } else {
            for (int cj = ci - 1; cj >= 0; --cj) {
                unsigned zz = ~Mr[cj];
                if (zz) { ld = (ci - cj) * 32 + b - (31 - __clz(zz)); break; }
            }
        }
        int rd = BIG;                                          // nearest zero >= w
        z = (~Mr[ci]) >> b;
        if (z) {
            rd = __ffs(z) - 1;
        } else {
            for (int cj = ci + 1; cj < 8; ++cj) {
                unsigned zz = ~Mr[cj];
                if (zz) { rd = cj * 32 + (__ffs(zz) - 1) - w; break; }
            }
        }
        gdst[i] = (unsigned short)min(min(ld, rd), BIG);
    }
}

// ---------------- Kernel 2: pass B ----------------
#define K2_COLS 16
#define K2_THREADS 256

__global__ __launch_bounds__(K2_THREADS)
void k2_passB(float* __restrict__ out) {
    __shared__ unsigned short gt[HH * K2_COLS];   // 8 KB tile: [row][col]
    __shared__ float red[K2_THREADS / 32];
    const int stripsPerSlice = WW / K2_COLS;      // 16
    const int slice = blockIdx.x / stripsPerSlice;
    const int st    = blockIdx.x % stripsPerSlice;
    const int c0    = st * K2_COLS;
    const int tid   = threadIdx.x;

    const unsigned short* gsrc = g_scratch + (size_t)slice * NPIX;

    // load 256x16 u16 tile as uint4 (8 u16 per load): 2 loads/thread
    {
        int r = tid;                                           // 256 rows, one per thread
        uint4 v0 = *reinterpret_cast<const uint4*>(gsrc + r * WW + c0);
        uint4 v1 = *reinterpret_cast<const uint4*>(gsrc + r * WW + c0 + 8);
        uint4* t4 = reinterpret_cast<uint4*>(gt + r * K2_COLS);
        t4[0] = v0;
        t4[1] = v1;
    }
    __syncthreads();

    const float wts[3] = {0.5f, 1.0f, 2.0f};
    const float wc = wts[slice % 3];
    float* dst = out + (size_t)slice * NPIX;

    float lmax = 0.0f;
    #pragma unroll
    for (int it = 0; it < (HH * K2_COLS) / K2_THREADS; ++it) {
        int i = it * K2_THREADS + tid;
        int r = i >> 4, c = i & 15;
        int gv   = (int)gt[r * K2_COLS + c];
        int best = gv * gv;
        for (int d = 1; d < HH; ++d) {
            int dd = d * d;
            if (dd >= best) break;                // exact: candidates are >= d^2
            int up = r - d, dn = r + d;
            if (up >= 0) { int cu = (int)gt[up * K2_COLS + c]; best = min(best, cu * cu + dd); }
            if (dn < HH) { int cd = (int)gt[dn * K2_COLS + c]; best = min(best, cd * cd + dd); }
        }
        float dt = wc * sqrtf((float)best);
        dst[r * WW + c0 + c] = dt;
        lmax = fmaxf(lmax, dt);
    }

    #pragma unroll
    for (int o = 16; o; o >>= 1) lmax = fmaxf(lmax, __shfl_xor_sync(0xffffffffu, lmax, o));
    if ((tid & 31) == 0) red[tid >> 5] = lmax;
    __syncthreads();
    if (tid < 8) {
        float v = red[tid];
        #pragma unroll
        for (int o = 4; o; o >>= 1) v = fmaxf(v, __shfl_xor_sync(0x000000ffu, v, o));
        if (tid == 0) atomicMax(&mx_bits[slice], __float_as_uint(v));  // dt>=0: bit-monotone
    }
}

// ---------------- Kernel 3: normalize ----------------
#define K3_THREADS 256

__global__ __launch_bounds__(K3_THREADS)
void k3_norm(float* __restrict__ out) {
    const int slice = blockIdx.x >> 4;            // 16 blocks per slice
    const int bl    = blockIdx.x & 15;
    const float mx  = __uint_as_float(mx_bits[slice]);
    const float inv = (mx > 0.0f) ? (1.0f / mx) : 0.0f;   // mx==0 -> dt==0 -> out 0

    float4* p = reinterpret_cast<float4*>(out) + (size_t)slice * (NPIX / 4) + bl * 1024;
    #pragma unroll
    for (int k = 0; k < 4; ++k) {
        int j = k * K3_THREADS + threadIdx.x;
        float4 v = p[j];
        v.x = (mx - v.x) * inv;
        v.y = (mx - v.y) * inv;
        v.z = (mx - v.z) * inv;
        v.w = (mx - v.w) * inv;
        p[j] = v;
    }
}

extern "C" void kernel_launch(void* const* d_in, const int* in_sizes, int n_in,
                              void* d_out, int out_size) {
    const float* in = (const float*)d_in[0];
    float* out = (float*)d_out;
    const int nslices = in_sizes[0] / NPIX;       // 48 for [16,3,256,256]

    k1_passA<<<nslices * (HH / K1_ROWS), K1_THREADS>>>(in);
    k2_passB<<<nslices * (WW / K2_COLS), K2_THREADS>>>(out);
    k3_norm <<<nslices * 16,             K3_THREADS>>>(out);
}

// round 4
// speedup vs baseline: 3.0306x; 1.0986x over previous
#include <cuda_runtime.h>

// WeightedDistanceTransform — 3-kernel pipeline, bitmask dataflow.
// k1: stream input -> 1-bit foreground mask (96 KB total; L2-resident)
// k2: per 16-col strip: smem bitmask -> g^2 on the fly (clz/ffs) -> exact
//     vertical min-plus with sound early exit -> dt + per-slice atomicMax
// k3: inverted normalize (mx - dt)/mx.

#define HH 256
#define WW 256
#define NPIX (HH * WW)
#define BIG 512
#define MAXSLICES 64
#define WPR 8                      // 32-bit words per row

__device__ unsigned int maskbuf[MAXSLICES * HH * WPR];   // 1 bit/px: 2 KB per slice
__device__ unsigned int mx_bits[MAXSLICES];

// ---------------- Kernel 1: mask pack (pure streaming) ----------------
#define K1_THREADS 256

__global__ __launch_bounds__(K1_THREADS)
void k1_mask(const float* __restrict__ in) {
    // grid = nslices * 16; each CTA: 16 rows = 4096 px, 16 px/thread
    const int slice = blockIdx.x >> 4;
    const int rb    = blockIdx.x & 15;
    const int tid   = threadIdx.x;

    if (rb == 0 && tid == 0) mx_bits[slice] = 0u;        // reset before k2

    const float4* s4 = reinterpret_cast<const float4*>(in)
                     + (size_t)slice * (NPIX / 4) + (size_t)rb * 1024 + tid * 4;
    float4 a = s4[0], b = s4[1], c = s4[2], d = s4[3];
    unsigned m = 0;
    m |= (a.x != 0.0f) << 0;  m |= (a.y != 0.0f) << 1;
    m |= (a.z != 0.0f) << 2;  m |= (a.w != 0.0f) << 3;
    m |= (b.x != 0.0f) << 4;  m |= (b.y != 0.0f) << 5;
    m |= (b.z != 0.0f) << 6;  m |= (b.w != 0.0f) << 7;
    m |= (c.x != 0.0f) << 8;  m |= (c.y != 0.0f) << 9;
    m |= (c.z != 0.0f) << 10; m |= (c.w != 0.0f) << 11;
    m |= (d.x != 0.0f) << 12; m |= (d.y != 0.0f) << 13;
    m |= (d.z != 0.0f) << 14; m |= (d.w != 0.0f) << 15;
    unsigned other = __shfl_xor_sync(0xffffffffu, m, 1);
    if ((tid & 1) == 0) {
        maskbuf[slice * (HH * WPR) + rb * 128 + (tid >> 1)] = m | (other << 16);
    }
}

// ---------------- Kernel 2: g^2 on the fly + vertical min-plus ----------------
#define K2_COLS 16
#define K2_THREADS 256

__global__ __launch_bounds__(K2_THREADS)
void k2_passB(float* __restrict__ out) {
    __shared__ unsigned int M[HH * WPR];          // 2 KB: whole-slice bitmask
    __shared__ unsigned int g2[HH * K2_COLS];     // 16 KB: g^2 tile [row][col]
    __shared__ float red[K2_THREADS / 32];

    const int slice = blockIdx.x >> 4;            // 16 strips per slice
    const int st    = blockIdx.x & 15;
    const int c0    = st * K2_COLS;
    const int tid   = threadIdx.x;

    // load slice bitmask: 2048 words... (HH*WPR = 2048) -> 8 words/thread
    {
        const unsigned int* src = maskbuf + slice * (HH * WPR);
        #pragma unroll
        for (int k = 0; k < (HH * WPR) / K2_THREADS; ++k)
            M[k * K2_THREADS + tid] = src[k * K2_THREADS + tid];
    }
    __syncthreads();

    // compute g^2 for the strip: 16 px/thread via clz/ffs on row bitmask
    #pragma unroll
    for (int it = 0; it < (HH * K2_COLS) / K2_THREADS; ++it) {
        int i = it * K2_THREADS + tid;
        int r = i >> 4;
        int w = c0 + (i & 15);
        const unsigned int* Mr = M + r * WPR;
        int ci = w >> 5, b = w & 31;

        int ld = BIG;                                          // nearest zero <= w
        unsigned lmask = (b == 31) ? 0xffffffffu : ((2u << b) - 1u);
        unsigned z = (~Mr[ci]) & lmask;
        if (z) {
            ld = b - (31 - __clz(z));
        } else {
            for (int cj = ci - 1; cj >= 0; --cj) {
                unsigned zz = ~Mr[cj];
                if (zz) { ld = (ci - cj) * 32 + b - (31 - __clz(zz)); break; }
            }
        }
        int rd = BIG;                                          // nearest zero >= w
        z = (~Mr[ci]) >> b;
        if (z) {
            rd = __ffs(z) - 1;
        } else {
            for (int cj = ci + 1; cj < WPR; ++cj) {
                unsigned zz = ~Mr[cj];
                if (zz) { rd = cj * 32 + (__ffs(zz) - 1) - w; break; }
            }
        }
        int g = min(min(ld, rd), BIG);
        g2[r * K2_COLS + (i & 15)] = (unsigned)(g * g);
    }
    __syncthreads();

    const float wts[3] = {0.5f, 1.0f, 2.0f};
    const float wc = wts[slice % 3];
    float* dst = out + (size_t)slice * NPIX;

    float lmax = 0.0f;
    #pragma unroll
    for (int it = 0; it < (HH * K2_COLS) / K2_THREADS; ++it) {
        int i = it * K2_THREADS + tid;
        int r = i >> 4, c = i & 15;
        int best = (int)g2[r * K2_COLS + c];
        for (int d = 1; d < HH; ++d) {
            int dd = d * d;
            if (dd >= best) break;                // exact: candidates are >= d^2
            int up = r - d, dn = r + d;
            if (up >= 0) best = min(best, (int)g2[up * K2_COLS + c] + dd);
            if (dn < HH) best = min(best, (int)g2[dn * K2_COLS + c] + dd);
        }
        float dt = wc * sqrtf((float)best);
        dst[r * WW + c0 + c] = dt;
        lmax = fmaxf(lmax, dt);
    }

    #pragma unroll
    for (int o = 16; o; o >>= 1) lmax = fmaxf(lmax, __shfl_xor_sync(0xffffffffu, lmax, o));
    if ((tid & 31) == 0) red[tid >> 5] = lmax;
    __syncthreads();
    if (tid < 8) {
        float v = red[tid];
        #pragma unroll
        for (int o = 4; o; o >>= 1) v = fmaxf(v, __shfl_xor_sync(0x000000ffu, v, o));
        if (tid == 0) atomicMax(&mx_bits[slice], __float_as_uint(v));  // dt>=0: bit-monotone
    }
}

// ---------------- Kernel 3: normalize ----------------
#define K3_THREADS 256

__global__ __launch_bounds__(K3_THREADS)
void k3_norm(float* __restrict__ out) {
    const int slice = blockIdx.x >> 4;
    const int bl    = blockIdx.x & 15;
    const float mx  = __uint_as_float(mx_bits[slice]);
    const float inv = (mx > 0.0f) ? (1.0f / mx) : 0.0f;   // mx==0 -> dt==0 -> out 0

    float4* p = reinterpret_cast<float4*>(out) + (size_t)slice * (NPIX / 4) + bl * 1024;
    #pragma unroll
    for (int k = 0; k < 4; ++k) {
        int j = k * K3_THREADS + threadIdx.x;
        float4 v = p[j];
        v.x = (mx - v.x) * inv;
        v.y = (mx - v.y) * inv;
        v.z = (mx - v.z) * inv;
        v.w = (mx - v.w) * inv;
        p[j] = v;
    }
}

extern "C" void kernel_launch(void* const* d_in, const int* in_sizes, int n_in,
                              void* d_out, int out_size) {
    const float* in = (const float*)d_in[0];
    float* out = (float*)d_out;
    const int nslices = in_sizes[0] / NPIX;       // 48 for [16,3,256,256]

    k1_mask <<<nslices * 16, K1_THREADS>>>(in);
    k2_passB<<<nslices * 16, K2_THREADS>>>(out);
    k3_norm <<<nslices * 16, K3_THREADS>>>(out);
}